// round 1
// baseline (speedup 1.0000x reference)
#include <cuda_runtime.h>

// ---------------- constants ----------------
#define D0 65
#define DD 4225          // 65*65
#define DDD 274625       // 65*65*65
#define S 32
#define SSS 32768        // 32^3
#define NB 2
#define C2 32
#define CO 100
#define G 16             // sites per block in invconv
#define LIST_STRIDE 72000

// ---------------- static scratch ----------------
__device__ float g_h1[NB*SSS*C2];   // channels-last [n][z][y][x][c]
__device__ float g_h2[NB*SSS*C2];
__device__ float g_m1[NB*SSS];
__device__ float g_W2T[27*32*32];   // [tap][ci][co]
__device__ float g_WT[27*32*100];   // [tap][ci][co]
__device__ float g_a1[32], g_k1[32], g_a2[32], g_k2[32];
__device__ int   g_list[8*LIST_STRIDE];
__device__ int   g_cnt[8];

// ---------------- prep: fold BN, transpose weights, reset counters ----------------
__global__ void prep_kernel(const float* __restrict__ W2, const float* __restrict__ Winv,
                            const float* __restrict__ b1, const float* __restrict__ g1,
                            const float* __restrict__ bt1, const float* __restrict__ rm1,
                            const float* __restrict__ rv1,
                            const float* __restrict__ b2, const float* __restrict__ g2,
                            const float* __restrict__ bt2, const float* __restrict__ rm2,
                            const float* __restrict__ rv2) {
    int tid = blockIdx.x * blockDim.x + threadIdx.x;
    int nth = gridDim.x * blockDim.x;
    if (tid < 8) g_cnt[tid] = 0;
    if (tid < 32) {
        float a = g1[tid] * rsqrtf(rv1[tid] + 1e-5f);
        g_a1[tid] = a;
        g_k1[tid] = (b1[tid] - rm1[tid]) * a + bt1[tid];
        float a2 = g2[tid] * rsqrtf(rv2[tid] + 1e-5f);
        g_a2[tid] = a2;
        g_k2[tid] = (b2[tid] - rm2[tid]) * a2 + bt2[tid];
    }
    // W2T[tap][ci][co] = W2[co][ci][tap]
    for (int i = tid; i < 27 * 32 * 32; i += nth) {
        int k = i / 1024, r = i % 1024, ci = r / 32, co = r % 32;
        g_W2T[i] = W2[(co * 32 + ci) * 27 + k];
    }
    // WT[tap][ci][co] = Winv[co][ci][tap]
    for (int i = tid; i < 27 * 32 * 100; i += nth) {
        int k = i / 3200, r = i % 3200, ci = r / 100, co = r % 100;
        g_WT[i] = Winv[(co * 32 + ci) * 27 + k];
    }
}

// ---------------- conv1 + BN + ReLU + mask ----------------
// block = 128 threads (x32 * y4), grid = (8, 32, 2)
__global__ void conv1_kernel(const float* __restrict__ x, const int* __restrict__ mask0,
                             const float* __restrict__ W1) {
    __shared__ float w1s[27 * 32];   // [tap][c]
    __shared__ float a1s[32], k1s[32];
    int tid = threadIdx.x;
    for (int i = tid; i < 864; i += 128) {
        int k = i >> 5, c = i & 31;
        w1s[i] = W1[c * 27 + k];
    }
    if (tid < 32) { a1s[tid] = g_a1[tid]; k1s[tid] = g_k1[tid]; }
    __syncthreads();

    int ox = tid & 31;
    int oy = blockIdx.x * 4 + (tid >> 5);
    int oz = blockIdx.y;
    int n  = blockIdx.z;

    float acc[32];
#pragma unroll
    for (int c = 0; c < 32; c++) acc[c] = 0.f;
    int cnt = 0;
    const float* xb = x + n * DDD;
    const int*   mb = mask0 + n * DDD;

    for (int kd = 0; kd < 3; kd++)
        for (int kh = 0; kh < 3; kh++) {
            int base = (2 * oz + kd) * DD + (2 * oy + kh) * D0 + 2 * ox;
#pragma unroll
            for (int kw = 0; kw < 3; kw++) {
                float v = xb[base + kw];
                cnt += mb[base + kw];
                const float* wq = &w1s[((kd * 3 + kh) * 3 + kw) * 32];
#pragma unroll
                for (int c = 0; c < 32; c++) acc[c] += v * wq[c];
            }
        }

    float m = (cnt > 0) ? 1.f : 0.f;
    int site = ((n * S + oz) * S + oy) * S + ox;
    g_m1[site] = m;
    float* hp = &g_h1[site * 32];
#pragma unroll
    for (int c = 0; c < 32; c++)
        hp[c] = fmaxf(acc[c] * a1s[c] + k1s[c], 0.f) * m;
}

// ---------------- build per-parity-class active lists from mask0 ----------------
__global__ void buildlist_kernel(const int* __restrict__ mask0) {
    int i = blockIdx.x * blockDim.x + threadIdx.x;
    if (i >= NB * DDD) return;
    if (mask0[i]) {
        int r = i % DDD;
        int oz = r / DD;
        int r2 = r % DD;
        int oy = r2 / D0;
        int ox = r2 % D0;
        int cls = ((oz & 1) << 2) | ((oy & 1) << 1) | (ox & 1);
        int p = atomicAdd(&g_cnt[cls], 1);
        g_list[cls * LIST_STRIDE + p] = i;
    }
}

// ---------------- conv2 (SubM) + BN + ReLU + mask ----------------
// block = 256 threads (x32 * y8), grid = (4, 32, 2), dyn smem = 27648 floats
__global__ __launch_bounds__(256) void conv2_kernel() {
    extern __shared__ float w2s[];
    __shared__ float a2s[32], k2s[32];
    int tid = threadIdx.x;
    for (int i = tid; i < 27 * 32 * 32; i += 256) w2s[i] = g_W2T[i];
    if (tid < 32) { a2s[tid] = g_a2[tid]; k2s[tid] = g_k2[tid]; }
    __syncthreads();

    int ox = tid & 31;
    int oy = blockIdx.x * 8 + (tid >> 5);
    int oz = blockIdx.y;
    int n  = blockIdx.z;

    float acc[32];
#pragma unroll
    for (int c = 0; c < 32; c++) acc[c] = 0.f;

    for (int kd = 0; kd < 3; kd++) {
        int zs = oz + kd - 1;
        if ((unsigned)zs >= 32u) continue;
        for (int kh = 0; kh < 3; kh++) {
            int ys = oy + kh - 1;
            bool yok = (unsigned)ys < 32u;
#pragma unroll
            for (int kw = 0; kw < 3; kw++) {
                int xs = ox + kw - 1;
                bool ok = yok && ((unsigned)xs < 32u);
                const float* hp = &g_h1[(((n * S + zs) * S + ys) * S + xs) * 32];
                const float* wp = &w2s[((kd * 3 + kh) * 3 + kw) * 1024];
#pragma unroll 4
                for (int ci = 0; ci < 32; ci++) {
                    float h = ok ? hp[ci] : 0.f;
                    const float4* wq = (const float4*)(wp + ci * 32);
#pragma unroll
                    for (int q = 0; q < 8; q++) {
                        float4 w = wq[q];
                        acc[q * 4 + 0] += h * w.x;
                        acc[q * 4 + 1] += h * w.y;
                        acc[q * 4 + 2] += h * w.z;
                        acc[q * 4 + 3] += h * w.w;
                    }
                }
            }
        }
    }

    int site = ((n * S + oz) * S + oy) * S + ox;
    float m = g_m1[site];
    float* op = &g_h2[site * 32];
#pragma unroll
    for (int c = 0; c < 32; c++)
        op[c] = fmaxf(acc[c] * a2s[c] + k2s[c], 0.f) * m;
}

// ---------------- zero-fill output ----------------
__global__ void zero_kernel(float4* __restrict__ out4, int n4, float* __restrict__ out, int rem_start, int total) {
    int i = blockIdx.x * blockDim.x + threadIdx.x;
    if (i < n4) out4[i] = make_float4(0.f, 0.f, 0.f, 0.f);
    if (i == 0) {
        for (int j = rem_start; j < total; j++) out[j] = 0.f;
    }
}

// ---------------- inverse (transposed stride-2) conv at active sites ----------------
// grid = (4500, 8): blockIdx.y = parity class; 128 threads (co = tid)
__global__ __launch_bounds__(128) void invconv_kernel(const float* __restrict__ binv,
                                                      float* __restrict__ out) {
    int cls = blockIdx.y;
    int count = g_cnt[cls];
    int base = blockIdx.x * G;
    if (base >= count) return;

    int pz = (cls >> 2) & 1, py = (cls >> 1) & 1, px = cls & 1;
    int ndz = pz ? 1 : 2, ndy = py ? 1 : 2, ndx = px ? 1 : 2;
    int numT = ndz * ndy * ndx;

    __shared__ float h2s[G * 8 * 32];
    __shared__ int   sbase[G * 8];
    __shared__ int   kmap[8];
    __shared__ int   ssite[G];

    int tid = threadIdx.x;
    int ng = count - base;
    if (ng > G) ng = G;

    if (tid < ng) ssite[tid] = g_list[cls * LIST_STRIDE + base + tid];
    if (tid < numT) {
        int t = tid;
        int tz = t / (ndy * ndx), ty = (t / ndx) % ndy, tx = t % ndx;
        int kd = pz ? 1 : tz * 2, kh = py ? 1 : ty * 2, kw = px ? 1 : tx * 2;
        kmap[t] = (kd * 3 + kh) * 3 + kw;
    }
    __syncthreads();

    // per-(site, tap) gather base addresses (-1 = out of bounds)
    for (int i = tid; i < ng * numT; i += 128) {
        int g = i / numT, t = i % numT;
        int s = ssite[g];
        int n = s / DDD;
        int r = s % DDD;
        int oz = r / DD;
        int r2 = r % DD;
        int oy = r2 / D0;
        int ox = r2 % D0;
        int tz = t / (ndy * ndx), ty = (t / ndx) % ndy, tx = t % ndx;
        int kd = pz ? 1 : tz * 2, kh = py ? 1 : ty * 2, kw = px ? 1 : tx * 2;
        int iz = (oz + kd - 2) >> 1;
        int iy = (oy + kh - 2) >> 1;
        int ix = (ox + kw - 2) >> 1;
        bool v = ((unsigned)iz < 32u) && ((unsigned)iy < 32u) && ((unsigned)ix < 32u);
        sbase[g * 8 + t] = v ? ((((n * S + iz) * S + iy) * S + ix) * 32) : -1;
    }
    __syncthreads();

    // cooperative load of h2 tap rows into shared (coalesced: lane = ci)
    for (int i = tid; i < G * numT * 32; i += 128) {
        int ci = i & 31;
        int gt = i >> 5;
        int g = gt / numT, t = gt % numT;
        int b = (g < ng) ? sbase[g * 8 + t] : -1;
        h2s[g * 256 + t * 32 + ci] = (b >= 0) ? g_h2[b + ci] : 0.f;
    }
    __syncthreads();

    int co = tid;
    bool cok = (co < CO);
    float bv = cok ? __ldg(&binv[co]) : 0.f;
    float acc[G];
#pragma unroll
    for (int g = 0; g < G; g++) acc[g] = bv;

    for (int t = 0; t < numT; t++) {
        const float* wp = g_WT + kmap[t] * 3200 + co;
        const float* hh = &h2s[t * 32];
#pragma unroll 4
        for (int ci = 0; ci < 32; ci++) {
            float w = cok ? __ldg(wp + ci * 100) : 0.f;
            const float* hc = hh + ci;
#pragma unroll
            for (int g = 0; g < G; g++) acc[g] += hc[g * 256] * w;
        }
    }

    if (cok) {
#pragma unroll
        for (int g = 0; g < G; g++) {
            if (g < ng) {
                int s = ssite[g];
                int n = s / DDD;
                int r = s % DDD;
                out[(n * CO + co) * DDD + r] = acc[g];
            }
        }
    }
}

// ---------------- launch ----------------
extern "C" void kernel_launch(void* const* d_in, const int* in_sizes, int n_in,
                              void* d_out, int out_size) {
    const float* x    = (const float*)d_in[0];
    const int*   mask0 = (const int*)d_in[1];
    const float* W1   = (const float*)d_in[2];
    const float* b1   = (const float*)d_in[3];
    const float* g1   = (const float*)d_in[4];
    const float* bt1  = (const float*)d_in[5];
    const float* rm1  = (const float*)d_in[6];
    const float* rv1  = (const float*)d_in[7];
    const float* W2   = (const float*)d_in[8];
    const float* b2   = (const float*)d_in[9];
    const float* g2   = (const float*)d_in[10];
    const float* bt2  = (const float*)d_in[11];
    const float* rm2  = (const float*)d_in[12];
    const float* rv2  = (const float*)d_in[13];
    const float* Winv = (const float*)d_in[14];
    const float* binv = (const float*)d_in[15];
    float* out = (float*)d_out;

    cudaFuncSetAttribute(conv2_kernel, cudaFuncAttributeMaxDynamicSharedMemorySize,
                         27 * 32 * 32 * (int)sizeof(float));

    prep_kernel<<<64, 256>>>(W2, Winv, b1, g1, bt1, rm1, rv1, b2, g2, bt2, rm2, rv2);
    conv1_kernel<<<dim3(8, 32, 2), 128>>>(x, mask0, W1);
    buildlist_kernel<<<(NB * DDD + 255) / 256, 256>>>(mask0);
    conv2_kernel<<<dim3(4, 32, 2), 256, 27 * 32 * 32 * sizeof(float)>>>();

    int n4 = out_size >> 2;
    zero_kernel<<<(n4 + 255) / 256, 256>>>((float4*)d_out, n4, out, n4 << 2, out_size);

    invconv_kernel<<<dim3((LIST_STRIDE + G - 1) / G, 8), 128>>>(binv, out);
}

// round 2
// speedup vs baseline: 2.3874x; 2.3874x over previous
#include <cuda_runtime.h>

// ---------------- constants ----------------
#define D0 65
#define DD 4225          // 65*65
#define DDD 274625       // 65*65*65
#define S 32
#define SSS 32768        // 32^3
#define NB 2
#define C2 32
#define CO 100
#define G 32             // sites per block in invconv
#define LIST_STRIDE 72000

// ---------------- static scratch ----------------
__device__ float g_h1[NB*C2*SSS];   // PLANAR [n][c][z][y][x]
__device__ float g_h2[NB*SSS*C2];   // channels-last [n][z][y][x][c]
__device__ float g_m1[NB*SSS];
__device__ float g_W2T[27*32*32];   // [tap][ci][co]
__device__ float g_WT[27*32*100];   // [tap][ci][co]
__device__ float g_a1[32], g_k1[32], g_a2[32], g_k2[32];
__device__ int   g_list[8*LIST_STRIDE];
__device__ int   g_cnt[8];

// ---------------- f32x2 helpers ----------------
__device__ __forceinline__ void ffma2(unsigned long long &d, unsigned long long a, unsigned long long b) {
    asm("fma.rn.f32x2 %0, %1, %2, %0;" : "+l"(d) : "l"(a), "l"(b));
}
__device__ __forceinline__ unsigned long long pack2(float x) {
    unsigned long long r;
    asm("mov.b64 %0, {%1, %1};" : "=l"(r) : "f"(x));
    return r;
}
__device__ __forceinline__ float2 unpack2(unsigned long long v) {
    float2 r;
    asm("mov.b64 {%0, %1}, %2;" : "=f"(r.x), "=f"(r.y) : "l"(v));
    return r;
}

// ---------------- prep: fold BN, transpose weights, reset counters ----------------
__global__ void prep_kernel(const float* __restrict__ W2, const float* __restrict__ Winv,
                            const float* __restrict__ b1, const float* __restrict__ g1,
                            const float* __restrict__ bt1, const float* __restrict__ rm1,
                            const float* __restrict__ rv1,
                            const float* __restrict__ b2, const float* __restrict__ g2,
                            const float* __restrict__ bt2, const float* __restrict__ rm2,
                            const float* __restrict__ rv2) {
    int tid = blockIdx.x * blockDim.x + threadIdx.x;
    int nth = gridDim.x * blockDim.x;
    if (tid < 8) g_cnt[tid] = 0;
    if (tid < 32) {
        float a = g1[tid] * rsqrtf(rv1[tid] + 1e-5f);
        g_a1[tid] = a;
        g_k1[tid] = (b1[tid] - rm1[tid]) * a + bt1[tid];
        float a2 = g2[tid] * rsqrtf(rv2[tid] + 1e-5f);
        g_a2[tid] = a2;
        g_k2[tid] = (b2[tid] - rm2[tid]) * a2 + bt2[tid];
    }
    for (int i = tid; i < 27 * 32 * 32; i += nth) {
        int k = i / 1024, r = i % 1024, ci = r / 32, co = r % 32;
        g_W2T[i] = W2[(co * 32 + ci) * 27 + k];
    }
    for (int i = tid; i < 27 * 32 * 100; i += nth) {
        int k = i / 3200, r = i % 3200, ci = r / 100, co = r % 100;
        g_WT[i] = Winv[(co * 32 + ci) * 27 + k];
    }
}

// ---------------- conv1 + BN + ReLU + mask (writes PLANAR h1) ----------------
// block = 128 threads (x32 * y4), grid = (8, 32, 2)
__global__ void conv1_kernel(const float* __restrict__ x, const int* __restrict__ mask0,
                             const float* __restrict__ W1) {
    __shared__ float w1s[27 * 32];   // [tap][c]
    __shared__ float a1s[32], k1s[32];
    int tid = threadIdx.x;
    for (int i = tid; i < 864; i += 128) {
        int k = i >> 5, c = i & 31;
        w1s[i] = W1[c * 27 + k];
    }
    if (tid < 32) { a1s[tid] = g_a1[tid]; k1s[tid] = g_k1[tid]; }
    __syncthreads();

    int ox = tid & 31;
    int oy = blockIdx.x * 4 + (tid >> 5);
    int oz = blockIdx.y;
    int n  = blockIdx.z;

    float acc[32];
#pragma unroll
    for (int c = 0; c < 32; c++) acc[c] = 0.f;
    int cnt = 0;
    const float* xb = x + n * DDD;
    const int*   mb = mask0 + n * DDD;

    for (int kd = 0; kd < 3; kd++)
        for (int kh = 0; kh < 3; kh++) {
            int base = (2 * oz + kd) * DD + (2 * oy + kh) * D0 + 2 * ox;
#pragma unroll
            for (int kw = 0; kw < 3; kw++) {
                float v = xb[base + kw];
                cnt += mb[base + kw];
                const float* wq = &w1s[((kd * 3 + kh) * 3 + kw) * 32];
#pragma unroll
                for (int c = 0; c < 32; c++) acc[c] += v * wq[c];
            }
        }

    float m = (cnt > 0) ? 1.f : 0.f;
    int loc = (oz * S + oy) * S + ox;
    g_m1[n * SSS + loc] = m;
    float* hp = &g_h1[n * (C2 * SSS) + loc];
#pragma unroll
    for (int c = 0; c < 32; c++)
        hp[c * SSS] = fmaxf(acc[c] * a1s[c] + k1s[c], 0.f) * m;
}

// ---------------- build per-parity-class active lists from mask0 ----------------
__global__ void buildlist_kernel(const int* __restrict__ mask0) {
    int i = blockIdx.x * blockDim.x + threadIdx.x;
    if (i >= NB * DDD) return;
    if (mask0[i]) {
        int r = i % DDD;
        int oz = r / DD;
        int r2 = r % DD;
        int oy = r2 / D0;
        int ox = r2 % D0;
        int cls = ((oz & 1) << 2) | ((oy & 1) << 1) | (ox & 1);
        int p = atomicAdd(&g_cnt[cls], 1);
        g_list[cls * LIST_STRIDE + p] = i;
    }
}

// ---------------- conv2 (SubM) + BN + ReLU + mask, f32x2 ----------------
// block = 256 threads (x32 * y8), grid = (4, 32, 2), dyn smem = 27*1024 floats
__global__ __launch_bounds__(256) void conv2_kernel() {
    extern __shared__ float w2s[];   // [tap][ci][co]
    __shared__ float a2s[32], k2s[32];
    int tid = threadIdx.x;
    {
        const float4* src = (const float4*)g_W2T;
        float4* dst = (float4*)w2s;
        for (int i = tid; i < 27 * 32 * 8; i += 256) dst[i] = src[i];
    }
    if (tid < 32) { a2s[tid] = g_a2[tid]; k2s[tid] = g_k2[tid]; }
    __syncthreads();

    int ox = tid & 31;
    int oy = blockIdx.x * 8 + (tid >> 5);
    int oz = blockIdx.y;
    int n  = blockIdx.z;

    unsigned long long acc2[16];
#pragma unroll
    for (int i = 0; i < 16; i++) acc2[i] = 0ull;

    const float* hbase = g_h1 + n * (C2 * SSS);

    for (int kd = 0; kd < 3; kd++) {
        int zs = oz + kd - 1;
        if ((unsigned)zs >= 32u) continue;
        for (int kh = 0; kh < 3; kh++) {
            int ys = oy + kh - 1;
            bool yok = (unsigned)ys < 32u;
            int rowoff = zs * 1024 + ys * 32;
#pragma unroll
            for (int kw = 0; kw < 3; kw++) {
                int xs = ox + kw - 1;
                bool ok = yok && ((unsigned)xs < 32u);
                const float* hp = hbase + rowoff + xs;
                const float* wp = &w2s[((kd * 3 + kh) * 3 + kw) * 1024];
#pragma unroll 4
                for (int ci = 0; ci < 32; ci++) {
                    float h = ok ? hp[ci * SSS] : 0.f;
                    unsigned long long hh = pack2(h);
                    const ulonglong2* wq = (const ulonglong2*)(wp + ci * 32);
#pragma unroll
                    for (int q = 0; q < 8; q++) {
                        ulonglong2 wv = wq[q];
                        ffma2(acc2[2 * q],     wv.x, hh);
                        ffma2(acc2[2 * q + 1], wv.y, hh);
                    }
                }
            }
        }
    }

    int loc = (oz * S + oy) * S + ox;
    float m = g_m1[n * SSS + loc];
    float* op = &g_h2[(n * SSS + loc) * 32];
#pragma unroll
    for (int j = 0; j < 16; j++) {
        float2 v = unpack2(acc2[j]);
        int c0 = 2 * j, c1 = 2 * j + 1;
        op[c0] = fmaxf(v.x * a2s[c0] + k2s[c0], 0.f) * m;
        op[c1] = fmaxf(v.y * a2s[c1] + k2s[c1], 0.f) * m;
    }
}

// ---------------- zero-fill output ----------------
__global__ void zero_kernel(float4* __restrict__ out4, int n4, float* __restrict__ out, int rem_start, int total) {
    int i = blockIdx.x * blockDim.x + threadIdx.x;
    if (i < n4) out4[i] = make_float4(0.f, 0.f, 0.f, 0.f);
    if (i == 0) {
        for (int j = rem_start; j < total; j++) out[j] = 0.f;
    }
}

// ---------------- inverse (transposed stride-2) conv at active sites, f32x2 ----------------
// grid = (2250, 8): blockIdx.y = parity class; 128 threads (co = tid)
__global__ __launch_bounds__(128) void invconv_kernel(const float* __restrict__ binv,
                                                      float* __restrict__ out) {
    int cls = blockIdx.y;
    int count = g_cnt[cls];
    int base = blockIdx.x * G;
    if (base >= count) return;

    int pz = (cls >> 2) & 1, py = (cls >> 1) & 1, px = cls & 1;
    int ndz = pz ? 1 : 2, ndy = py ? 1 : 2, ndx = px ? 1 : 2;
    int numT = ndz * ndy * ndx;

    __shared__ float h2s[8 * 32 * 36];   // [t][ci][pad36] g fastest
    __shared__ int   sbase[G * 8];
    __shared__ int   kmap[8];
    __shared__ int   ssite[G];
    __shared__ int   sout[G];

    int tid = threadIdx.x;
    int ng = count - base;
    if (ng > G) ng = G;

    if (tid < ng) {
        int s = g_list[cls * LIST_STRIDE + base + tid];
        ssite[tid] = s;
        sout[tid] = s + ((s >= DDD) ? 99 * DDD : 0);   // n*CO*DDD + r (co added later)
    }
    if (tid < numT) {
        int t = tid;
        int tz = t / (ndy * ndx), ty = (t / ndx) % ndy, tx = t % ndx;
        int kd = pz ? 1 : tz * 2, kh = py ? 1 : ty * 2, kw = px ? 1 : tx * 2;
        kmap[t] = (kd * 3 + kh) * 3 + kw;
    }
    __syncthreads();

    for (int i = tid; i < ng * numT; i += 128) {
        int g = i / numT, t = i % numT;
        int s = ssite[g];
        int n = s / DDD;
        int r = s % DDD;
        int oz = r / DD;
        int r2 = r % DD;
        int oy = r2 / D0;
        int ox = r2 % D0;
        int tz = t / (ndy * ndx), ty = (t / ndx) % ndy, tx = t % ndx;
        int kd = pz ? 1 : tz * 2, kh = py ? 1 : ty * 2, kw = px ? 1 : tx * 2;
        int iz = (oz + kd - 2) >> 1;
        int iy = (oy + kh - 2) >> 1;
        int ix = (ox + kw - 2) >> 1;
        bool v = ((unsigned)iz < 32u) && ((unsigned)iy < 32u) && ((unsigned)ix < 32u);
        sbase[g * 8 + t] = v ? ((((n * S + iz) * S + iy) * S + ix) * 32) : -1;
    }
    __syncthreads();

    // cooperative load of h2 tap rows (source ci-coalesced, dest [t][ci][g])
    for (int i = tid; i < G * numT * 32; i += 128) {
        int ci = i & 31;
        int gt = i >> 5;
        int g = gt / numT, t = gt % numT;
        int b = (g < ng) ? sbase[g * 8 + t] : -1;
        h2s[(t * 32 + ci) * 36 + g] = (b >= 0) ? g_h2[b + ci] : 0.f;
    }
    __syncthreads();

    int co = tid;
    bool cok = (co < CO);
    float bv = cok ? __ldg(&binv[co]) : 0.f;
    unsigned long long acc2[16];
    unsigned long long bb = pack2(bv);
#pragma unroll
    for (int j = 0; j < 16; j++) acc2[j] = bb;

    for (int t = 0; t < numT; t++) {
        const float* wp = g_WT + kmap[t] * 3200 + co;
        const float* hb = &h2s[(t * 32) * 36];
#pragma unroll 4
        for (int ci = 0; ci < 32; ci++) {
            float w = cok ? __ldg(wp + ci * 100) : 0.f;
            unsigned long long ww = pack2(w);
            const ulonglong2* hq = (const ulonglong2*)(hb + ci * 36);
#pragma unroll
            for (int q = 0; q < 8; q++) {
                ulonglong2 hv = hq[q];
                ffma2(acc2[2 * q],     ww, hv.x);
                ffma2(acc2[2 * q + 1], ww, hv.y);
            }
        }
    }

    if (cok) {
        int cd = co * DDD;
#pragma unroll
        for (int j = 0; j < 16; j++) {
            float2 v = unpack2(acc2[j]);
            int g0 = 2 * j, g1 = 2 * j + 1;
            if (g0 < ng) out[sout[g0] + cd] = v.x;
            if (g1 < ng) out[sout[g1] + cd] = v.y;
        }
    }
}

// ---------------- launch ----------------
extern "C" void kernel_launch(void* const* d_in, const int* in_sizes, int n_in,
                              void* d_out, int out_size) {
    const float* x    = (const float*)d_in[0];
    const int*   mask0 = (const int*)d_in[1];
    const float* W1   = (const float*)d_in[2];
    const float* b1   = (const float*)d_in[3];
    const float* g1   = (const float*)d_in[4];
    const float* bt1  = (const float*)d_in[5];
    const float* rm1  = (const float*)d_in[6];
    const float* rv1  = (const float*)d_in[7];
    const float* W2   = (const float*)d_in[8];
    const float* b2   = (const float*)d_in[9];
    const float* g2   = (const float*)d_in[10];
    const float* bt2  = (const float*)d_in[11];
    const float* rm2  = (const float*)d_in[12];
    const float* rv2  = (const float*)d_in[13];
    const float* Winv = (const float*)d_in[14];
    const float* binv = (const float*)d_in[15];
    float* out = (float*)d_out;

    cudaFuncSetAttribute(conv2_kernel, cudaFuncAttributeMaxDynamicSharedMemorySize,
                         27 * 32 * 32 * (int)sizeof(float));

    prep_kernel<<<64, 256>>>(W2, Winv, b1, g1, bt1, rm1, rv1, b2, g2, bt2, rm2, rv2);
    conv1_kernel<<<dim3(8, 32, 2), 128>>>(x, mask0, W1);
    buildlist_kernel<<<(NB * DDD + 255) / 256, 256>>>(mask0);
    conv2_kernel<<<dim3(4, 32, 2), 256, 27 * 32 * 32 * sizeof(float)>>>();

    int n4 = out_size >> 2;
    zero_kernel<<<(n4 + 255) / 256, 256>>>((float4*)d_out, n4, out, n4 << 2, out_size);

    invconv_kernel<<<dim3((LIST_STRIDE + G - 1) / G, 8), 128>>>(binv, out);
}

// round 3
// speedup vs baseline: 2.5136x; 1.0528x over previous
#include <cuda_runtime.h>

// ---------------- constants ----------------
#define D0 65
#define DD 4225          // 65*65
#define DDD 274625       // 65*65*65
#define S 32
#define SSS 32768        // 32^3
#define NB 2
#define C2 32
#define CO 100
#define G 32             // sites per block in invconv
#define LIST_STRIDE 8192

// ---------------- static scratch ----------------
__device__ float g_h1[NB*C2*SSS];   // PLANAR [n][c][z][y][x]
__device__ float g_h2[NB*SSS*C2];   // channels-last [n][z][y][x][c]
__device__ float g_m1[NB*SSS];
__device__ float g_W2T[27*32*32];   // [tap][ci][co]
__device__ float g_WT[27*32*100];   // [tap][ci][co]
__device__ float g_a1[32], g_k1[32], g_a2[32], g_k2[32];
__device__ int   g_list[8*LIST_STRIDE];
__device__ int   g_slot[NB*DDD];    // voxel -> compact slot (or -1)
__device__ float g_comp[8*LIST_STRIDE*CO]; // compact invconv output [slot][co]
__device__ int   g_cnt[8];

// ---------------- f32x2 helpers ----------------
__device__ __forceinline__ void ffma2(unsigned long long &d, unsigned long long a, unsigned long long b) {
    asm("fma.rn.f32x2 %0, %1, %2, %0;" : "+l"(d) : "l"(a), "l"(b));
}
__device__ __forceinline__ unsigned long long pack2(float x) {
    unsigned long long r;
    asm("mov.b64 %0, {%1, %1};" : "=l"(r) : "f"(x));
    return r;
}
__device__ __forceinline__ float2 unpack2(unsigned long long v) {
    float2 r;
    asm("mov.b64 {%0, %1}, %2;" : "=f"(r.x), "=f"(r.y) : "l"(v));
    return r;
}

// ---------------- prep: fold BN, transpose weights, reset counters, fill slot=-1 ----------------
__global__ void prep_kernel(const float* __restrict__ W2, const float* __restrict__ Winv,
                            const float* __restrict__ b1, const float* __restrict__ g1,
                            const float* __restrict__ bt1, const float* __restrict__ rm1,
                            const float* __restrict__ rv1,
                            const float* __restrict__ b2, const float* __restrict__ g2,
                            const float* __restrict__ bt2, const float* __restrict__ rm2,
                            const float* __restrict__ rv2) {
    int tid = blockIdx.x * blockDim.x + threadIdx.x;
    int nth = gridDim.x * blockDim.x;
    if (tid < 8) g_cnt[tid] = 0;
    if (tid < 32) {
        float a = g1[tid] * rsqrtf(rv1[tid] + 1e-5f);
        g_a1[tid] = a;
        g_k1[tid] = (b1[tid] - rm1[tid]) * a + bt1[tid];
        float a2 = g2[tid] * rsqrtf(rv2[tid] + 1e-5f);
        g_a2[tid] = a2;
        g_k2[tid] = (b2[tid] - rm2[tid]) * a2 + bt2[tid];
    }
    for (int i = tid; i < 27 * 32 * 32; i += nth) {
        int k = i / 1024, r = i % 1024, ci = r / 32, co = r % 32;
        g_W2T[i] = W2[(co * 32 + ci) * 27 + k];
    }
    for (int i = tid; i < 27 * 32 * 100; i += nth) {
        int k = i / 3200, r = i % 3200, ci = r / 100, co = r % 100;
        g_WT[i] = Winv[(co * 32 + ci) * 27 + k];
    }
    for (int i = tid; i < NB * DDD; i += nth) g_slot[i] = -1;
}

// ---------------- conv1 + BN + ReLU + mask (writes PLANAR h1) ----------------
// block = 128 threads (x32 * y4), grid = (8, 32, 2)
__global__ void conv1_kernel(const float* __restrict__ x, const int* __restrict__ mask0,
                             const float* __restrict__ W1) {
    __shared__ float w1s[27 * 32];   // [tap][c]
    __shared__ float a1s[32], k1s[32];
    int tid = threadIdx.x;
    for (int i = tid; i < 864; i += 128) {
        int k = i >> 5, c = i & 31;
        w1s[i] = W1[c * 27 + k];
    }
    if (tid < 32) { a1s[tid] = g_a1[tid]; k1s[tid] = g_k1[tid]; }
    __syncthreads();

    int ox = tid & 31;
    int oy = blockIdx.x * 4 + (tid >> 5);
    int oz = blockIdx.y;
    int n  = blockIdx.z;

    float acc[32];
#pragma unroll
    for (int c = 0; c < 32; c++) acc[c] = 0.f;
    int cnt = 0;
    const float* xb = x + n * DDD;
    const int*   mb = mask0 + n * DDD;

    for (int kd = 0; kd < 3; kd++)
        for (int kh = 0; kh < 3; kh++) {
            int base = (2 * oz + kd) * DD + (2 * oy + kh) * D0 + 2 * ox;
#pragma unroll
            for (int kw = 0; kw < 3; kw++) {
                float v = xb[base + kw];
                cnt += mb[base + kw];
                const float* wq = &w1s[((kd * 3 + kh) * 3 + kw) * 32];
#pragma unroll
                for (int c = 0; c < 32; c++) acc[c] += v * wq[c];
            }
        }

    float m = (cnt > 0) ? 1.f : 0.f;
    int loc = (oz * S + oy) * S + ox;
    g_m1[n * SSS + loc] = m;
    float* hp = &g_h1[n * (C2 * SSS) + loc];
#pragma unroll
    for (int c = 0; c < 32; c++)
        hp[c * SSS] = fmaxf(acc[c] * a1s[c] + k1s[c], 0.f) * m;
}

// ---------------- build per-parity-class active lists + inverse slot map ----------------
__global__ void buildlist_kernel(const int* __restrict__ mask0) {
    int i = blockIdx.x * blockDim.x + threadIdx.x;
    if (i >= NB * DDD) return;
    if (mask0[i]) {
        int r = i % DDD;
        int oz = r / DD;
        int r2 = r % DD;
        int oy = r2 / D0;
        int ox = r2 % D0;
        int cls = ((oz & 1) << 2) | ((oy & 1) << 1) | (ox & 1);
        int p = atomicAdd(&g_cnt[cls], 1);
        int slot = cls * LIST_STRIDE + p;
        g_list[slot] = i;
        g_slot[i] = slot;
    }
}

// ---------------- conv2 (SubM) + BN + ReLU + mask, f32x2, 2 x-sites per thread ------
// block = 128 threads (x16 * y8), grid = (4, 32, 2), dyn smem = 27*1024 floats
__global__ __launch_bounds__(128) void conv2_kernel() {
    extern __shared__ float w2s[];   // [tap][ci][co]
    __shared__ float a2s[32], k2s[32];
    int tid = threadIdx.x;
    {
        const float4* src = (const float4*)g_W2T;
        float4* dst = (float4*)w2s;
        for (int i = tid; i < 27 * 32 * 8; i += 128) dst[i] = src[i];
    }
    if (tid < 32) { a2s[tid] = g_a2[tid]; k2s[tid] = g_k2[tid]; }
    __syncthreads();

    int xh = tid & 15;               // site pair ox0 = 2*xh, ox1 = 2*xh+1
    int oy = blockIdx.x * 8 + (tid >> 4);
    int oz = blockIdx.y;
    int n  = blockIdx.z;

    unsigned long long accA[16], accB[16];
#pragma unroll
    for (int i = 0; i < 16; i++) { accA[i] = 0ull; accB[i] = 0ull; }

    const float* hbase = g_h1 + n * (C2 * SSS);
    int xm1 = 2 * xh - 1;            // base x offset (j=0..3 covers xm1..xm1+3)
    bool x0ok = (xh != 0);           // j=0 valid?
    bool x3ok = (xh != 15);          // j=3 valid?

    for (int kd = 0; kd < 3; kd++) {
        int zs = oz + kd - 1;
        if ((unsigned)zs >= 32u) continue;
        for (int kh = 0; kh < 3; kh++) {
            int ys = oy + kh - 1;
            bool yok = (unsigned)ys < 32u;
            const float* rowp = hbase + zs * 1024 + ys * 32 + xm1;
            int tap0 = (kd * 3 + kh) * 3;
#pragma unroll 2
            for (int ci = 0; ci < 32; ci++) {
                const float* rp = rowp + ci * SSS;
                float h0 = (yok && x0ok) ? rp[0] : 0.f;
                float h1v = yok ? rp[1] : 0.f;
                float h2v = yok ? rp[2] : 0.f;
                float h3 = (yok && x3ok) ? rp[3] : 0.f;
                unsigned long long hh0 = pack2(h0);
                unsigned long long hh1 = pack2(h1v);
                unsigned long long hh2 = pack2(h2v);
                unsigned long long hh3 = pack2(h3);
                const ulonglong2* wq0 = (const ulonglong2*)&w2s[(tap0 + 0) * 1024 + ci * 32];
                const ulonglong2* wq1 = (const ulonglong2*)&w2s[(tap0 + 1) * 1024 + ci * 32];
                const ulonglong2* wq2 = (const ulonglong2*)&w2s[(tap0 + 2) * 1024 + ci * 32];
#pragma unroll
                for (int q = 0; q < 8; q++) {
                    ulonglong2 w0 = wq0[q];
                    ulonglong2 w1 = wq1[q];
                    ulonglong2 w2 = wq2[q];
                    // site0 uses h[j=kw], site1 uses h[j=kw+1]
                    ffma2(accA[2 * q],     w0.x, hh0);
                    ffma2(accA[2 * q + 1], w0.y, hh0);
                    ffma2(accB[2 * q],     w0.x, hh1);
                    ffma2(accB[2 * q + 1], w0.y, hh1);
                    ffma2(accA[2 * q],     w1.x, hh1);
                    ffma2(accA[2 * q + 1], w1.y, hh1);
                    ffma2(accB[2 * q],     w1.x, hh2);
                    ffma2(accB[2 * q + 1], w1.y, hh2);
                    ffma2(accA[2 * q],     w2.x, hh2);
                    ffma2(accA[2 * q + 1], w2.y, hh2);
                    ffma2(accB[2 * q],     w2.x, hh3);
                    ffma2(accB[2 * q + 1], w2.y, hh3);
                }
            }
        }
    }

    int loc0 = (oz * S + oy) * S + 2 * xh;
    float m0 = g_m1[n * SSS + loc0];
    float m1v = g_m1[n * SSS + loc0 + 1];
    float* op0 = &g_h2[(n * SSS + loc0) * 32];
    float* op1 = op0 + 32;
#pragma unroll
    for (int j = 0; j < 16; j++) {
        float2 va = unpack2(accA[j]);
        float2 vb = unpack2(accB[j]);
        int c0 = 2 * j, c1 = 2 * j + 1;
        op0[c0] = fmaxf(va.x * a2s[c0] + k2s[c0], 0.f) * m0;
        op0[c1] = fmaxf(va.y * a2s[c1] + k2s[c1], 0.f) * m0;
        op1[c0] = fmaxf(vb.x * a2s[c0] + k2s[c0], 0.f) * m1v;
        op1[c1] = fmaxf(vb.y * a2s[c1] + k2s[c1], 0.f) * m1v;
    }
}

// ---------------- inverse conv at active sites -> compact buffer, f32x2 -------------
// grid = (256, 8): blockIdx.y = parity class; 128 threads (co = tid)
__global__ __launch_bounds__(128) void invconv_kernel(const float* __restrict__ binv) {
    int cls = blockIdx.y;
    int count = g_cnt[cls];
    int base = blockIdx.x * G;
    if (base >= count) return;

    int pz = (cls >> 2) & 1, py = (cls >> 1) & 1, px = cls & 1;
    int ndz = pz ? 1 : 2, ndy = py ? 1 : 2, ndx = px ? 1 : 2;
    int numT = ndz * ndy * ndx;

    __shared__ float h2s[8 * 32 * 36];   // [t][ci][pad36], g fastest
    __shared__ int   sbase[G * 8];
    __shared__ int   kmap[8];
    __shared__ int   ssite[G];

    int tid = threadIdx.x;
    int ng = count - base;
    if (ng > G) ng = G;

    if (tid < ng) ssite[tid] = g_list[cls * LIST_STRIDE + base + tid];
    if (tid < numT) {
        int t = tid;
        int tz = t / (ndy * ndx), ty = (t / ndx) % ndy, tx = t % ndx;
        int kd = pz ? 1 : tz * 2, kh = py ? 1 : ty * 2, kw = px ? 1 : tx * 2;
        kmap[t] = (kd * 3 + kh) * 3 + kw;
    }
    __syncthreads();

    for (int i = tid; i < ng * numT; i += 128) {
        int g = i / numT, t = i % numT;
        int s = ssite[g];
        int n = s / DDD;
        int r = s % DDD;
        int oz = r / DD;
        int r2 = r % DD;
        int oy = r2 / D0;
        int ox = r2 % D0;
        int tz = t / (ndy * ndx), ty = (t / ndx) % ndy, tx = t % ndx;
        int kd = pz ? 1 : tz * 2, kh = py ? 1 : ty * 2, kw = px ? 1 : tx * 2;
        int iz = (oz + kd - 2) >> 1;
        int iy = (oy + kh - 2) >> 1;
        int ix = (ox + kw - 2) >> 1;
        bool v = ((unsigned)iz < 32u) && ((unsigned)iy < 32u) && ((unsigned)ix < 32u);
        sbase[g * 8 + t] = v ? ((((n * S + iz) * S + iy) * S + ix) * 32) : -1;
    }
    __syncthreads();

    for (int i = tid; i < G * numT * 32; i += 128) {
        int ci = i & 31;
        int gt = i >> 5;
        int g = gt / numT, t = gt % numT;
        int b = (g < ng) ? sbase[g * 8 + t] : -1;
        h2s[(t * 32 + ci) * 36 + g] = (b >= 0) ? g_h2[b + ci] : 0.f;
    }
    __syncthreads();

    int co = tid;
    bool cok = (co < CO);
    float bv = cok ? __ldg(&binv[co]) : 0.f;
    unsigned long long acc2[16];
    unsigned long long bb = pack2(bv);
#pragma unroll
    for (int j = 0; j < 16; j++) acc2[j] = bb;

    for (int t = 0; t < numT; t++) {
        const float* wp = g_WT + kmap[t] * 3200 + co;
        const float* hb = &h2s[(t * 32) * 36];
#pragma unroll 4
        for (int ci = 0; ci < 32; ci++) {
            float w = cok ? __ldg(wp + ci * 100) : 0.f;
            unsigned long long ww = pack2(w);
            const ulonglong2* hq = (const ulonglong2*)(hb + ci * 36);
#pragma unroll
            for (int q = 0; q < 8; q++) {
                ulonglong2 hv = hq[q];
                ffma2(acc2[2 * q],     ww, hv.x);
                ffma2(acc2[2 * q + 1], ww, hv.y);
            }
        }
    }

    if (cok) {
        int slotbase = cls * LIST_STRIDE + base;
#pragma unroll
        for (int j = 0; j < 16; j++) {
            float2 v = unpack2(acc2[j]);
            int g0 = 2 * j, g1 = 2 * j + 1;
            if (g0 < ng) g_comp[(slotbase + g0) * CO + co] = v.x;
            if (g1 < ng) g_comp[(slotbase + g1) * CO + co] = v.y;
        }
    }
}

// ---------------- output writer: stream 220MB, value-or-zero ----------------
// block 256, grid (ceil(DDD/1024), NB)
__global__ __launch_bounds__(256) void writer_kernel(float* __restrict__ out) {
    __shared__ int slots[1024];
    int n  = blockIdx.y;
    int s0 = blockIdx.x * 1024;
    int ns = DDD - s0; if (ns > 1024) ns = 1024;
    int tid = threadIdx.x;
    for (int i = tid; i < 1024; i += 256)
        slots[i] = (i < ns) ? g_slot[n * DDD + s0 + i] : -1;
    __syncthreads();

    float* ob = out + (size_t)n * CO * DDD + s0;
    for (int co = 0; co < CO; co++) {
        float* oc = ob + (size_t)co * DDD;
#pragma unroll
        for (int k = 0; k < 4; k++) {
            int i = k * 256 + tid;
            if (i < ns) {
                int sl = slots[i];
                oc[i] = (sl >= 0) ? g_comp[sl * CO + co] : 0.f;
            }
        }
    }
}

// ---------------- launch ----------------
extern "C" void kernel_launch(void* const* d_in, const int* in_sizes, int n_in,
                              void* d_out, int out_size) {
    const float* x    = (const float*)d_in[0];
    const int*   mask0 = (const int*)d_in[1];
    const float* W1   = (const float*)d_in[2];
    const float* b1   = (const float*)d_in[3];
    const float* g1   = (const float*)d_in[4];
    const float* bt1  = (const float*)d_in[5];
    const float* rm1  = (const float*)d_in[6];
    const float* rv1  = (const float*)d_in[7];
    const float* W2   = (const float*)d_in[8];
    const float* b2   = (const float*)d_in[9];
    const float* g2   = (const float*)d_in[10];
    const float* bt2  = (const float*)d_in[11];
    const float* rm2  = (const float*)d_in[12];
    const float* rv2  = (const float*)d_in[13];
    const float* Winv = (const float*)d_in[14];
    const float* binv = (const float*)d_in[15];
    float* out = (float*)d_out;

    cudaFuncSetAttribute(conv2_kernel, cudaFuncAttributeMaxDynamicSharedMemorySize,
                         27 * 32 * 32 * (int)sizeof(float));

    prep_kernel<<<64, 256>>>(W2, Winv, b1, g1, bt1, rm1, rv1, b2, g2, bt2, rm2, rv2);
    conv1_kernel<<<dim3(8, 32, 2), 128>>>(x, mask0, W1);
    buildlist_kernel<<<(NB * DDD + 255) / 256, 256>>>(mask0);
    conv2_kernel<<<dim3(4, 32, 2), 128, 27 * 32 * 32 * sizeof(float)>>>();
    invconv_kernel<<<dim3(LIST_STRIDE / G, 8), 128>>>(binv);
    writer_kernel<<<dim3((DDD + 1023) / 1024, NB), 256>>>(out);
}